// round 10
// baseline (speedup 1.0000x reference)
#include <cuda_runtime.h>

// Problem constants
#define NQPTS 4096
#define HID   1024
#define RR    4096   // R*K = R*R = 64*64
#define NPTS  16384
#define SUBS  128    // P1 sub-blocks per MLP
#define HC2   32     // P2 h-chunks (32 rows each)
#define NB    148    // persistent grid size (<= SM count, 1 block/SM resident)

// ---------------- scratch (device globals; no allocation allowed) ----------
__device__ __align__(16)  float g_part[2][SUBS][HID]; // per-task partial t-sums
__device__ __align__(128) float g_ysum[2][SUBS];      // per-task partial y-sums
__device__ __align__(16)  float g_Spart[2][HC2][RR];  // h-chunked partial S
__device__ __align__(16)  float g_S[2][RR];           // reduced S0, S1
__device__ __align__(16)  float g_r[RR];              // rhs flattened [64*64]
__device__ __align__(128) float g_v[HID];             // Wx2 @ r
__device__ __align__(128) float g_cpart[16];          // partial bx2 . r
__device__ __align__(128) float g_c;                  // bx2 . r

// ---------------- software grid barrier ------------------------------------
__device__ int g_bar_count;
__device__ volatile int g_bar_gen;

__device__ __forceinline__ void grid_sync()
{
    __syncthreads();
    if (threadIdx.x == 0) {
        __threadfence();
        int gen = g_bar_gen;
        if (atomicAdd(&g_bar_count, 1) == NB - 1) {
            atomicExch(&g_bar_count, 0);
            __threadfence();
            g_bar_gen = gen + 1;
        } else {
            while (g_bar_gen == gen) { }
        }
        __threadfence();
    }
    __syncthreads();
}

__device__ __forceinline__ float tanh_fast(float x) {
    float y;
    asm("tanh.approx.f32 %0, %1;" : "=f"(y) : "f"(x));
    return y;
}

// Forced-order loads: volatile asm pins issue order -> guaranteed deep MLP.
__device__ __forceinline__ float4 ldg4(const float4* p) {
    float4 v;
    asm volatile("ld.global.nc.v4.f32 {%0,%1,%2,%3}, [%4];"
                 : "=f"(v.x), "=f"(v.y), "=f"(v.z), "=f"(v.w) : "l"(p));
    return v;
}
__device__ __forceinline__ float ldgf(const float* p) {
    float v;
    asm volatile("ld.global.nc.f32 %0, [%1];" : "=f"(v) : "l"(p));
    return v;
}
// L2-only load for same-launch multi-writer cache lines (L1 may be stale).
__device__ __forceinline__ float ldcg(const float* p) {
    float v;
    asm volatile("ld.global.cg.f32 %0, [%1];" : "=f"(v) : "l"(p));
    return v;
}

// ---------------------------------------------------------------------------
// One persistent kernel; 5 phases separated by grid barriers.
// ---------------------------------------------------------------------------
__global__ void __launch_bounds__(256, 1)
fused_all(const float* __restrict__ input, const float* __restrict__ eq,
          const float* __restrict__ qx0,  const float* __restrict__ qx1,
          const float* __restrict__ Wx1,  const float* __restrict__ bx1,
          const float* __restrict__ Wx2,  const float* __restrict__ bx2,
          const float* __restrict__ Wq0a, const float* __restrict__ bq0a,
          const float* __restrict__ Wq0b, const float* __restrict__ bq0b,
          const float* __restrict__ Wq1a, const float* __restrict__ bq1a,
          const float* __restrict__ Wq1b, const float* __restrict__ bq1b,
          float* __restrict__ out)
{
    __shared__ __align__(16) char sm[20608];
    const int bid = blockIdx.x;
    const int tid = threadIdx.x;

    // ======================= P1: quad layer-1 + weighted t ==================
    {
        const float eqv = ldgf(eq);
        float* sx0 = (float*)sm;
        float* sx1 = sx0 + 32;
        float* sx2 = sx1 + 32;
        float* sy  = sx2 + 32;
        for (int task = bid; task < 256; task += NB) {
            const int mlp = task >> 7;
            const int sub = task & (SUBS - 1);
            const float* __restrict__ qx = mlp ? qx1 : qx0;
            const float* __restrict__ W  = mlp ? Wq1a : Wq0a;
            const float* __restrict__ B  = mlp ? bq1a : bq0a;
            const int base = sub * 32;

            __syncthreads();
            if (tid < 32) {
                float x0 = qx[(base + tid) * 3 + 0];
                float x1 = qx[(base + tid) * 3 + 1];
                float x2 = qx[(base + tid) * 3 + 2];
                sx0[tid] = x0; sx1[tid] = x1; sx2[tid] = x2;
                sy[tid]  = __expf(-eqv * (x0 * x0 + x1 * x1 + x2 * x2));
            }
            __syncthreads();

            float w0[4], w1[4], w2[4], bb[4], acc[4];
#pragma unroll
            for (int k = 0; k < 4; k++) {
                int h = tid + 256 * k;
                w0[k] = ldgf(W + h);
                w1[k] = ldgf(W + HID + h);
                w2[k] = ldgf(W + 2 * HID + h);
                bb[k] = ldgf(B + h);
                acc[k] = 0.0f;
            }
#pragma unroll 4
            for (int p = 0; p < 32; p++) {
                float x0 = sx0[p], x1 = sx1[p], x2 = sx2[p], y = sy[p];
#pragma unroll
                for (int k = 0; k < 4; k++) {
                    float a = fmaf(x0, w0[k], fmaf(x1, w1[k], fmaf(x2, w2[k], bb[k])));
                    acc[k] = fmaf(y, tanh_fast(a), acc[k]);
                }
            }
#pragma unroll
            for (int k = 0; k < 4; k++)
                g_part[mlp][sub][tid + 256 * k] = acc[k];
            if (tid == 0) {
                float s = 0.0f;
#pragma unroll
                for (int p = 0; p < 32; p++) s += sy[p];
                g_ysum[mlp][sub] = s;
            }
        }
    }
    grid_sync();

    // ======================= P2: Spart = t-chunk @ Wqb ======================
    if (bid < 128) {
        const int mlp = bid >> 6;
        const int rest = bid & 63;
        const int hc = rest >> 1;        // 0..31, 32 rows each
        const int jhalf = rest & 1;      // 2048 cols each half
        const float* __restrict__ W = mlp ? Wq1b : Wq0b;
        const float* __restrict__ B = mlp ? bq1b : bq0b;
        const int hbase = hc * 32;

        float (*tp)[32] = (float(*)[32])sm;          // 8x32
        float* tv   = (float*)(sm + 1024);           // 32
        float* sysp = (float*)(sm + 1024 + 128);     // 1

        {   // t reduction: 8 threads per h, 16 subs each, forced loads
            const int q = tid >> 5;      // 0..7
            const int h = tid & 31;
            const float* p = &g_part[mlp][q * 16][hbase + h];
            float s = 0.0f;
#pragma unroll
            for (int b2 = 0; b2 < 2; b2++) {
                float v[8];
#pragma unroll
                for (int u = 0; u < 8; u++)
                    v[u] = ldgf(p + (size_t)(b2 * 8 + u) * HID);
#pragma unroll
                for (int u = 0; u < 8; u++) s += v[u];
            }
            tp[q][h] = s;
        }
        __syncthreads();
        if (tid < 32) {
            float s = 0.0f;
#pragma unroll
            for (int q = 0; q < 8; q++) s += tp[q][tid];
            tv[tid] = s;
        }
        if (hc == 0 && tid >= 64 && tid < 96) {
            int l = tid - 64;
            float s = ldcg(&g_ysum[mlp][l])      + ldcg(&g_ysum[mlp][l + 32]) +
                      ldcg(&g_ysum[mlp][l + 64]) + ldcg(&g_ysum[mlp][l + 96]);
#pragma unroll
            for (int o = 16; o; o >>= 1) s += __shfl_xor_sync(0xffffffffu, s, o);
            if (l == 0) *sysp = s;
        }
        __syncthreads();

        const int col0 = jhalf * 512 + tid;   // float4 col
        const int col1 = col0 + 256;
        float a0, a1, a2, a3, c0, c1, c2, c3;
        if (hc == 0) {
            float ys = *sysp;
            float4 f0 = ldg4((const float4*)B + col0);
            float4 f1 = ldg4((const float4*)B + col1);
            a0 = ys * f0.x; a1 = ys * f0.y; a2 = ys * f0.z; a3 = ys * f0.w;
            c0 = ys * f1.x; c1 = ys * f1.y; c2 = ys * f1.z; c3 = ys * f1.w;
        } else {
            a0 = a1 = a2 = a3 = c0 = c1 = c2 = c3 = 0.0f;
        }
        const float4* __restrict__ W4 = (const float4*)W + (size_t)hbase * (RR / 4);
#pragma unroll
        for (int bb = 0; bb < 4; bb++) {
            float4 wA[8], wB[8];
#pragma unroll
            for (int u = 0; u < 8; u++)
                wA[u] = ldg4(W4 + (size_t)(bb * 8 + u) * (RR / 4) + col0);
#pragma unroll
            for (int u = 0; u < 8; u++)
                wB[u] = ldg4(W4 + (size_t)(bb * 8 + u) * (RR / 4) + col1);
#pragma unroll
            for (int u = 0; u < 8; u++) {
                float th = tv[bb * 8 + u];
                a0 = fmaf(th, wA[u].x, a0); a1 = fmaf(th, wA[u].y, a1);
                a2 = fmaf(th, wA[u].z, a2); a3 = fmaf(th, wA[u].w, a3);
                c0 = fmaf(th, wB[u].x, c0); c1 = fmaf(th, wB[u].y, c1);
                c2 = fmaf(th, wB[u].z, c2); c3 = fmaf(th, wB[u].w, c3);
            }
        }
        float4* dst = (float4*)&g_Spart[mlp][hc][0];
        dst[col0] = make_float4(a0, a1, a2, a3);
        dst[col1] = make_float4(c0, c1, c2, c3);
    }
    grid_sync();

    // ======================= P3a: reduce Spart -> S =========================
    {
        const int gid = bid * 256 + tid;
        if (gid < 2048) {
            const int mlp = gid >> 10;
            const int col = gid & 1023;
            const float4* __restrict__ base =
                (const float4*)g_Spart + (size_t)mlp * HC2 * (RR / 4) + col;
            float4 a = make_float4(0.f, 0.f, 0.f, 0.f);
#pragma unroll
            for (int b = 0; b < 4; b++) {
                float4 v[8];
#pragma unroll
                for (int u = 0; u < 8; u++)
                    v[u] = ldg4(base + (size_t)(b * 8 + u) * (RR / 4));
#pragma unroll
                for (int u = 0; u < 8; u++) {
                    a.x += v[u].x; a.y += v[u].y; a.z += v[u].z; a.w += v[u].w;
                }
            }
            ((float4*)g_S)[gid] = a;
        }
    }
    grid_sync();

    // ======================= P3b: r = S0 @ S1^T, cpart ======================
    if (bid < 16) {
        float* s1 = (float*)sm;                 // 64*65
        float* s0 = s1 + 64 * 65;               // 4*65
        float* p8 = (float*)(sm + 17696);       // 8 floats
        const int bbase = bid * 4;

        float4 vv[4];
        const float4* __restrict__ gS1 = (const float4*)&g_S[1][0];
#pragma unroll
        for (int k = 0; k < 4; k++)
            vv[k] = ldg4(gS1 + k * 256 + tid);
        float4 v0 = make_float4(0.f, 0.f, 0.f, 0.f);
        if (tid < 64)
            v0 = ldg4((const float4*)&g_S[0][bbase * 64] + tid);

#pragma unroll
        for (int k = 0; k < 4; k++) {
            int j4 = k * 256 + tid;
            float* dst = s1 + (j4 >> 4) * 65 + (j4 & 15) * 4;
            dst[0] = vv[k].x; dst[1] = vv[k].y; dst[2] = vv[k].z; dst[3] = vv[k].w;
        }
        if (tid < 64) {
            float* dst = s0 + (tid >> 4) * 65 + (tid & 15) * 4;
            dst[0] = v0.x; dst[1] = v0.y; dst[2] = v0.z; dst[3] = v0.w;
        }
        __syncthreads();

        const int b = tid >> 6;
        const int d = tid & 63;
        float acc = 0.0f;
#pragma unroll 16
        for (int x = 0; x < 64; x++)
            acc = fmaf(s0[b * 65 + x], s1[d * 65 + x], acc);
        const int o = (bbase + b) * 64 + d;
        g_r[o] = acc;

        float cacc = acc * bx2[o];
#pragma unroll
        for (int o2 = 16; o2; o2 >>= 1) cacc += __shfl_xor_sync(0xffffffffu, cacc, o2);
        if ((tid & 31) == 0) p8[tid >> 5] = cacc;
        __syncthreads();
        if (tid == 0) {
            float s = 0.0f;
#pragma unroll
            for (int i = 0; i < 8; i++) s += p8[i];
            g_cpart[bid] = s;
        }
    }
    grid_sync();

    // ======================= P4: v = Wx2 @ r, c =============================
    {
        if (bid == 147 && tid == 0) {
            float s = 0.0f;
#pragma unroll
            for (int i = 0; i < 16; i++) s += ldcg(&g_cpart[i]);
            g_c = s;
        }
        float* part = (float*)sm;
        const int row = tid >> 7;          // 0 or 1
        const int g = tid & 127;

        float4 rr[8];
#pragma unroll
        for (int k = 0; k < 8; k++)
            rr[k] = ldg4((const float4*)g_r + g + 128 * k);

        int t = bid;
        float4 w[8];
        {
            const float4* __restrict__ W4 =
                (const float4*)Wx2 + (size_t)(2 * t + row) * (RR / 4) + g;
#pragma unroll
            for (int k = 0; k < 8; k++) w[k] = ldg4(W4 + 128 * k);
        }
        while (t < 512) {
            const int tn = t + NB;
            float4 wn[8];
            if (tn < 512) {
                const float4* __restrict__ W4n =
                    (const float4*)Wx2 + (size_t)(2 * tn + row) * (RR / 4) + g;
#pragma unroll
                for (int k = 0; k < 8; k++) wn[k] = ldg4(W4n + 128 * k);
            }
            float acc = 0.0f;
#pragma unroll
            for (int k = 0; k < 8; k++) {
                acc = fmaf(w[k].x, rr[k].x, acc);
                acc = fmaf(w[k].y, rr[k].y, acc);
                acc = fmaf(w[k].z, rr[k].z, acc);
                acc = fmaf(w[k].w, rr[k].w, acc);
            }
#pragma unroll
            for (int o = 16; o; o >>= 1) acc += __shfl_xor_sync(0xffffffffu, acc, o);
            __syncthreads();
            if ((tid & 31) == 0) part[tid >> 5] = acc;
            __syncthreads();
            if (tid < 2)
                g_v[2 * t + tid] = part[4 * tid] + part[4 * tid + 1] +
                                   part[4 * tid + 2] + part[4 * tid + 3];
#pragma unroll
            for (int k = 0; k < 8; k++) w[k] = wn[k];
            t = tn;
        }
    }
    grid_sync();

    // ======================= P5: out = tanh(x@Wx1+b) . v + c ================
    {
        float4* swb = (float4*)sm;              // 1024 float4
        float*  sv  = (float*)(sm + 16384);     // 1024 floats
        {
            float a0[4], a1[4], a2[4], a3[4], a4[4];
#pragma unroll
            for (int k = 0; k < 4; k++) {
                int h = tid + 256 * k;
                a0[k] = ldgf(Wx1 + h);
                a1[k] = ldgf(Wx1 + HID + h);
                a2[k] = ldgf(Wx1 + 2 * HID + h);
                a3[k] = ldgf(bx1 + h);
                a4[k] = ldcg(&g_v[h]);
            }
#pragma unroll
            for (int k = 0; k < 4; k++) {
                int h = tid + 256 * k;
                swb[h] = make_float4(a0[k], a1[k], a2[k], a3[k]);
                sv[h] = a4[k];
            }
        }
        __syncthreads();
        const float c = ldcg(&g_c);
        const int warp = tid >> 5, lane = tid & 31;

        for (int t = bid; t < 512; t += NB) {
            const int nbase = (t * 8 + warp) * 4;
            float x0[4], x1[4], x2[4];
#pragma unroll
            for (int nn = 0; nn < 4; nn++) {
                x0[nn] = input[(nbase + nn) * 3 + 0];
                x1[nn] = input[(nbase + nn) * 3 + 1];
                x2[nn] = input[(nbase + nn) * 3 + 2];
            }
            float acc[4] = {0.0f, 0.0f, 0.0f, 0.0f};
#pragma unroll 4
            for (int k = 0; k < 32; k++) {
                int h = k * 32 + lane;
                float4 wb = swb[h];
                float vv = sv[h];
#pragma unroll
                for (int nn = 0; nn < 4; nn++) {
                    float a = fmaf(x0[nn], wb.x, fmaf(x1[nn], wb.y, fmaf(x2[nn], wb.z, wb.w)));
                    acc[nn] = fmaf(tanh_fast(a), vv, acc[nn]);
                }
            }
#pragma unroll
            for (int nn = 0; nn < 4; nn++) {
                float a = acc[nn];
#pragma unroll
                for (int o = 16; o; o >>= 1) a += __shfl_xor_sync(0xffffffffu, a, o);
                if (lane == 0) out[nbase + nn] = a + c;
            }
        }
    }
}

// ---------------------------------------------------------------------------
// Input order (metadata): 0 input, 1 eq_param, 2 quad_x0, 3 quad_x1,
// 4 Wx1, 5 bx1, 6 Wx2, 7 bx2, 8 Wq0a, 9 bq0a, 10 Wq0b, 11 bq0b,
// 12 Wq1a, 13 bq1a, 14 Wq1b, 15 bq1b
// ---------------------------------------------------------------------------
extern "C" void kernel_launch(void* const* d_in, const int* in_sizes, int n_in,
                              void* d_out, int out_size)
{
    const float* input  = (const float*)d_in[0];
    const float* eq     = (const float*)d_in[1];
    const float* qx0    = (const float*)d_in[2];
    const float* qx1    = (const float*)d_in[3];
    const float* Wx1    = (const float*)d_in[4];
    const float* bx1    = (const float*)d_in[5];
    const float* Wx2    = (const float*)d_in[6];
    const float* bx2    = (const float*)d_in[7];
    const float* Wq0a   = (const float*)d_in[8];
    const float* bq0a   = (const float*)d_in[9];
    const float* Wq0b   = (const float*)d_in[10];
    const float* bq0b   = (const float*)d_in[11];
    const float* Wq1a   = (const float*)d_in[12];
    const float* bq1a   = (const float*)d_in[13];
    const float* Wq1b   = (const float*)d_in[14];
    const float* bq1b   = (const float*)d_in[15];
    float* out = (float*)d_out;

    fused_all<<<NB, 256>>>(input, eq, qx0, qx1, Wx1, bx1, Wx2, bx2,
                           Wq0a, bq0a, Wq0b, bq0b, Wq1a, bq1a, Wq1b, bq1b, out);
}